// round 1
// baseline (speedup 1.0000x reference)
#include <cuda_runtime.h>

// y = exp(i * LZ * DPHI) * x, elementwise.
// ifft2(fft2(x) * scalar) == scalar * x by linearity of the FFT.
// LZ*DPHI = 0.05 -> c = cos(0.05) + i*sin(0.05)
//
// Inputs:  d_in[0] = x_real [B*M*N] f32, d_in[1] = x_imag [B*M*N] f32
// Output:  d_out [2*B*M*N] f32, first half = real(y), second half = imag(y)

#define COS_C 0.9987502603949663f
#define SIN_C 0.0499791692706783f

__global__ void __launch_bounds__(256, 8)
freq_shift_kernel(const float4* __restrict__ xr,
                  const float4* __restrict__ xi,
                  float4* __restrict__ yr,
                  float4* __restrict__ yi,
                  int n4)
{
    int i = blockIdx.x * blockDim.x + threadIdx.x;
    if (i >= n4) return;

    float4 r = xr[i];
    float4 m = xi[i];

    float4 orr, oii;
    orr.x = fmaf(r.x, COS_C, -m.x * SIN_C);
    orr.y = fmaf(r.y, COS_C, -m.y * SIN_C);
    orr.z = fmaf(r.z, COS_C, -m.z * SIN_C);
    orr.w = fmaf(r.w, COS_C, -m.w * SIN_C);

    oii.x = fmaf(r.x, SIN_C, m.x * COS_C);
    oii.y = fmaf(r.y, SIN_C, m.y * COS_C);
    oii.z = fmaf(r.z, SIN_C, m.z * COS_C);
    oii.w = fmaf(r.w, SIN_C, m.w * COS_C);

    yr[i] = orr;
    yi[i] = oii;
}

extern "C" void kernel_launch(void* const* d_in, const int* in_sizes, int n_in,
                              void* d_out, int out_size)
{
    const float* x_real = (const float*)d_in[0];
    const float* x_imag = (const float*)d_in[1];
    float* out = (float*)d_out;

    const int n = in_sizes[0];          // B*M*N = 33,554,432
    const int n4 = n / 4;               // elements are a multiple of 4

    float* out_real = out;
    float* out_imag = out + n;

    const int threads = 256;
    const int blocks = (n4 + threads - 1) / threads;

    freq_shift_kernel<<<blocks, threads>>>(
        (const float4*)x_real, (const float4*)x_imag,
        (float4*)out_real, (float4*)out_imag, n4);
}

// round 2
// speedup vs baseline: 1.0004x; 1.0004x over previous
#include <cuda_runtime.h>

// y = exp(i * LZ * DPHI) * x, elementwise.
// ifft2(fft2(x) * scalar) == scalar * x by linearity of the FFT.
// LZ*DPHI = 0.05 -> c = cos(0.05) + i*sin(0.05)
//
// Inputs:  d_in[0] = x_real [B*M*N] f32, d_in[1] = x_imag [B*M*N] f32
// Output:  d_out [2*B*M*N] f32, first half = real(y), second half = imag(y)
//
// Pure HBM-bound stream (536.9 MB total). Strategy: maximize per-thread MLP
// (4 outstanding 16B loads front-batched) + streaming cache hints (.cs) since
// the working set is 4x L2 and has zero reuse.

#define COS_C 0.9987502603949663f
#define SIN_C 0.0499791692706783f

__device__ __forceinline__ float4 ld_cs(const float4* p) {
    float4 v;
    asm volatile("ld.global.cs.v4.f32 {%0,%1,%2,%3}, [%4];"
                 : "=f"(v.x), "=f"(v.y), "=f"(v.z), "=f"(v.w)
                 : "l"(p));
    return v;
}

__device__ __forceinline__ void st_cs(float4* p, float4 v) {
    asm volatile("st.global.cs.v4.f32 [%0], {%1,%2,%3,%4};"
                 :: "l"(p), "f"(v.x), "f"(v.y), "f"(v.z), "f"(v.w)
                 : "memory");
}

__device__ __forceinline__ void rot(const float4& r, const float4& m,
                                    float4& orr, float4& oii) {
    orr.x = fmaf(r.x, COS_C, -m.x * SIN_C);
    orr.y = fmaf(r.y, COS_C, -m.y * SIN_C);
    orr.z = fmaf(r.z, COS_C, -m.z * SIN_C);
    orr.w = fmaf(r.w, COS_C, -m.w * SIN_C);
    oii.x = fmaf(r.x, SIN_C, m.x * COS_C);
    oii.y = fmaf(r.y, SIN_C, m.y * COS_C);
    oii.z = fmaf(r.z, SIN_C, m.z * COS_C);
    oii.w = fmaf(r.w, SIN_C, m.w * COS_C);
}

__global__ void __launch_bounds__(256, 8)
freq_shift_kernel(const float4* __restrict__ xr,
                  const float4* __restrict__ xi,
                  float4* __restrict__ yr,
                  float4* __restrict__ yi,
                  int half4)   // n4 / 2
{
    int i = blockIdx.x * blockDim.x + threadIdx.x;
    if (i >= half4) return;
    int j = i + half4;

    // Front-batch all four 16B loads: MLP = 4 before any dependent math.
    float4 r0 = ld_cs(xr + i);
    float4 r1 = ld_cs(xr + j);
    float4 m0 = ld_cs(xi + i);
    float4 m1 = ld_cs(xi + j);

    float4 or0, oi0, or1, oi1;
    rot(r0, m0, or0, oi0);
    rot(r1, m1, or1, oi1);

    st_cs(yr + i, or0);
    st_cs(yi + i, oi0);
    st_cs(yr + j, or1);
    st_cs(yi + j, oi1);
}

extern "C" void kernel_launch(void* const* d_in, const int* in_sizes, int n_in,
                              void* d_out, int out_size)
{
    const float* x_real = (const float*)d_in[0];
    const float* x_imag = (const float*)d_in[1];
    float* out = (float*)d_out;

    const int n = in_sizes[0];          // B*M*N = 33,554,432
    const int n4 = n / 4;
    const int half4 = n4 / 2;           // each thread handles 2 float4 per stream

    float* out_real = out;
    float* out_imag = out + n;

    const int threads = 256;
    const int blocks = (half4 + threads - 1) / threads;

    freq_shift_kernel<<<blocks, threads>>>(
        (const float4*)x_real, (const float4*)x_imag,
        (float4*)out_real, (float4*)out_imag, half4);
}